// round 1
// baseline (speedup 1.0000x reference)
#include <cuda_runtime.h>

// VectorQuantization: N=32768 rows of D=64 vs K=1024 codes.
// out = [quantized (N*D) | indices as float (N) | commitment_loss (1)]

#define NROWS 32768
#define D     64
#define K     1024
#define TC    128            // codes per shared-memory tile
#define RPB   64             // rows per block == threads per block
#define NBLK  (NROWS / RPB)  // 512 blocks

__device__ float g_wnorm[K];
__device__ float g_partial[NBLK];

static __device__ __forceinline__ unsigned long long ffma2(unsigned long long a,
                                                           unsigned long long b,
                                                           unsigned long long c) {
    unsigned long long d;
    asm("fma.rn.f32x2 %0, %1, %2, %3;" : "=l"(d) : "l"(a), "l"(b), "l"(c));
    return d;
}
static __device__ __forceinline__ unsigned long long fadd2(unsigned long long a,
                                                           unsigned long long b) {
    unsigned long long d;
    asm("add.rn.f32x2 %0, %1, %2;" : "=l"(d) : "l"(a), "l"(b));
    return d;
}
static __device__ __forceinline__ unsigned long long pack2(float lo, float hi) {
    unsigned long long r;
    asm("mov.b64 %0, {%1, %2};" : "=l"(r) : "f"(lo), "f"(hi));
    return r;
}
static __device__ __forceinline__ void unpack2(unsigned long long v, float& lo, float& hi) {
    asm("mov.b64 {%0, %1}, %2;" : "=f"(lo), "=f"(hi) : "l"(v));
}

// ---- Kernel A: per-code squared norms -------------------------------------
__global__ void vq_prep(const float* __restrict__ w) {
    int k = blockIdx.x * blockDim.x + threadIdx.x;
    if (k < K) {
        const float4* wr = reinterpret_cast<const float4*>(w + (size_t)k * D);
        float s = 0.f;
#pragma unroll
        for (int i = 0; i < 16; i++) {
            float4 v = wr[i];
            s = __fadd_rn(s, __fmul_rn(v.x, v.x));
            s = __fadd_rn(s, __fmul_rn(v.y, v.y));
            s = __fadd_rn(s, __fmul_rn(v.z, v.z));
            s = __fadd_rn(s, __fmul_rn(v.w, v.w));
        }
        g_wnorm[k] = s;
    }
}

// ---- Kernel B: argmin over codes + gather + STE output + loss partials ----
__global__ void __launch_bounds__(RPB) vq_main(const float* __restrict__ x,
                                               const float* __restrict__ w,
                                               float* __restrict__ out_q,
                                               float* __restrict__ out_idx,
                                               int has_idx) {
    __shared__ float s_w[TC * D];   // 32 KB code tile
    __shared__ float s_wn[TC];
    __shared__ float s_red[RPB];

    const int tid = threadIdx.x;
    const int row = blockIdx.x * RPB + tid;

    const float4* xrow = reinterpret_cast<const float4*>(x + (size_t)row * D);

    // Row into registers as 32 packed f32x2 values; sequential ||x||^2.
    unsigned long long xr[32];
    float xnorm = 0.f;
#pragma unroll
    for (int i = 0; i < 16; i++) {
        float4 v = xrow[i];
        xnorm = __fadd_rn(xnorm, __fmul_rn(v.x, v.x));
        xnorm = __fadd_rn(xnorm, __fmul_rn(v.y, v.y));
        xnorm = __fadd_rn(xnorm, __fmul_rn(v.z, v.z));
        xnorm = __fadd_rn(xnorm, __fmul_rn(v.w, v.w));
        xr[2 * i]     = pack2(v.x, v.y);
        xr[2 * i + 1] = pack2(v.z, v.w);
    }

    float best = 3.4e38f;
    int bidx = 0;

    for (int t = 0; t < K; t += TC) {
        __syncthreads();  // previous tile fully consumed
        const float4* wt = reinterpret_cast<const float4*>(w + (size_t)t * D);
        float4* sw4 = reinterpret_cast<float4*>(s_w);
#pragma unroll
        for (int i = 0; i < 32; i++) sw4[tid + i * RPB] = wt[tid + i * RPB];
        s_wn[tid]       = g_wnorm[t + tid];
        s_wn[tid + RPB] = g_wnorm[t + tid + RPB];
        __syncthreads();

#pragma unroll 2
        for (int kk = 0; kk < TC; kk++) {
            const ulonglong2* wrow =
                reinterpret_cast<const ulonglong2*>(s_w + kk * D);
            unsigned long long a0 = 0ull, a1 = 0ull, a2 = 0ull, a3 = 0ull;
#pragma unroll
            for (int j = 0; j < 8; j++) {
                ulonglong2 wv0 = wrow[2 * j];
                ulonglong2 wv1 = wrow[2 * j + 1];
                a0 = ffma2(xr[4 * j],     wv0.x, a0);
                a1 = ffma2(xr[4 * j + 1], wv0.y, a1);
                a2 = ffma2(xr[4 * j + 2], wv1.x, a2);
                a3 = ffma2(xr[4 * j + 3], wv1.y, a3);
            }
            a0 = fadd2(a0, a2);
            a1 = fadd2(a1, a3);
            a0 = fadd2(a0, a1);
            float dlo, dhi;
            unpack2(a0, dlo, dhi);
            float dot = __fadd_rn(dlo, dhi);
            // Match reference rounding: (||x||^2 + ||e||^2) - (2.0 * dot), no FMA fusion.
            float dist = __fsub_rn(__fadd_rn(xnorm, s_wn[kk]),
                                   __fmul_rn(2.0f, dot));
            if (dist < best) { best = dist; bidx = t + kk; }  // strict < => first min wins
        }
    }

    // Epilogue: gather winning code, straight-through output, loss partial.
    const float4* wb = reinterpret_cast<const float4*>(w + (size_t)bidx * D);
    float4* oq = reinterpret_cast<float4*>(out_q + (size_t)row * D);
    float lsum = 0.f;
#pragma unroll
    for (int i = 0; i < 16; i++) {
        float4 wv = wb[i];
        float4 xv = xrow[i];
        float4 dv, ov;
        dv.x = __fsub_rn(wv.x, xv.x);
        dv.y = __fsub_rn(wv.y, xv.y);
        dv.z = __fsub_rn(wv.z, xv.z);
        dv.w = __fsub_rn(wv.w, xv.w);
        ov.x = __fadd_rn(xv.x, dv.x);   // inputs + (quantized - inputs), as reference
        ov.y = __fadd_rn(xv.y, dv.y);
        ov.z = __fadd_rn(xv.z, dv.z);
        ov.w = __fadd_rn(xv.w, dv.w);
        lsum += dv.x * dv.x + dv.y * dv.y + dv.z * dv.z + dv.w * dv.w;
        oq[i] = ov;
    }
    if (has_idx) out_idx[row] = (float)bidx;

    // Deterministic block tree-reduce of loss partials.
    s_red[tid] = lsum;
    __syncthreads();
#pragma unroll
    for (int s = RPB / 2; s > 0; s >>= 1) {
        if (tid < s) s_red[tid] = __fadd_rn(s_red[tid], s_red[tid + s]);
        __syncthreads();
    }
    if (tid == 0) g_partial[blockIdx.x] = s_red[0];
}

// ---- Kernel C: final deterministic reduction -> commitment loss ------------
__global__ void vq_final(float* __restrict__ out_loss) {
    __shared__ float s[256];
    int tid = threadIdx.x;
    s[tid] = __fadd_rn(g_partial[tid], g_partial[tid + 256]);
    __syncthreads();
    for (int st = 128; st > 0; st >>= 1) {
        if (tid < st) s[tid] = __fadd_rn(s[tid], s[tid + st]);
        __syncthreads();
    }
    if (tid == 0) {
        float mean = s[0] / 2097152.0f;  // exact: power-of-two divisor
        *out_loss = 0.25f * (mean + mean);
    }
}

extern "C" void kernel_launch(void* const* d_in, const int* in_sizes, int n_in,
                              void* d_out, int out_size) {
    const float* x;
    const float* w;
    // Identify operands by element count (inputs: 2,097,152; weight: 65,536).
    if (n_in >= 2 && in_sizes[0] == K * D && in_sizes[1] != K * D) {
        w = (const float*)d_in[0];
        x = (const float*)d_in[1];
    } else {
        x = (const float*)d_in[0];
        w = (const float*)d_in[1];
    }

    float* out = (float*)d_out;
    const long ND = (long)NROWS * D;
    if (out_size < ND) return;  // unexpected layout; do nothing rather than corrupt

    int has_idx  = out_size >= ND + NROWS;
    int has_loss = out_size >= ND + NROWS + 1;

    vq_prep<<<4, 256>>>(w);
    vq_main<<<NBLK, RPB>>>(x, w, out, out + ND, has_idx);
    if (has_loss) vq_final<<<1, 256>>>(out + ND + NROWS);
}